// round 6
// baseline (speedup 1.0000x reference)
#include <cuda_runtime.h>
#include <cstdint>

#define B 8
#define K 19
#define C 512
#define S 16384

#define CT     32                      // channels per block
#define CHUNK  512                     // s-floats per probs pipeline stage
#define ZSPLIT 8                       // s-range split across blocks
#define SPB    (S / ZSPLIT)            // 2048 s per block
#define CPB    (SPB / CHUNK)           // 4 chunks per block
#define PROB_FLOATS (K * CHUNK)        // 9728
#define PROB_BYTES  (PROB_FLOATS * 4)  // 38912
#define SMEM_BYTES  (2 * PROB_BYTES)   // 77824

// Scratch
__device__ float g_probs[B * K * S];       // unnormalized exp(aux - rowmax)
__device__ float g_invsum[B * K];
__device__ float g_part[ZSPLIT][B * C * K];

// ---------------------------------------------------------------------------
// Kernel 1: per-(b,k) row: rowmax, e = exp(x - max) -> g_probs, 1/sum(e).
// ---------------------------------------------------------------------------
__global__ void __launch_bounds__(512) softmax_stats_kernel(const float* __restrict__ aux) {
    const int row = blockIdx.x;
    const float4* __restrict__ src = (const float4*)(aux + (size_t)row * S);
    float4* __restrict__ dst = (float4*)(g_probs + (size_t)row * S);
    const int tid = threadIdx.x;
    __shared__ float sred[16];
    __shared__ float smax;

    float m = -1e30f;
    #pragma unroll 4
    for (int i = tid; i < S / 4; i += 512) {
        float4 v = src[i];
        m = fmaxf(m, fmaxf(fmaxf(v.x, v.y), fmaxf(v.z, v.w)));
    }
    #pragma unroll
    for (int o = 16; o; o >>= 1) m = fmaxf(m, __shfl_xor_sync(0xffffffffu, m, o));
    if ((tid & 31) == 0) sred[tid >> 5] = m;
    __syncthreads();
    if (tid == 0) {
        float v = sred[0];
        #pragma unroll
        for (int w = 1; w < 16; ++w) v = fmaxf(v, sred[w]);
        smax = v;
    }
    __syncthreads();
    const float mx = smax;

    float sum = 0.f;
    #pragma unroll 4
    for (int i = tid; i < S / 4; i += 512) {
        float4 v = src[i];
        float4 e;
        e.x = __expf(v.x - mx);
        e.y = __expf(v.y - mx);
        e.z = __expf(v.z - mx);
        e.w = __expf(v.w - mx);
        dst[i] = e;
        sum += (e.x + e.y) + (e.z + e.w);
    }
    #pragma unroll
    for (int o = 16; o; o >>= 1) sum += __shfl_xor_sync(0xffffffffu, sum, o);
    if ((tid & 31) == 0) sred[tid >> 5] = sum;
    __syncthreads();
    if (tid == 0) {
        float t = 0.f;
        #pragma unroll
        for (int w = 0; w < 16; ++w) t += sred[w];
        g_invsum[row] = 1.0f / t;
    }
}

// ---------------------------------------------------------------------------
// Kernel 2: partial ctx over this block's s-range.
// probs: cp.async 2-stage smem pipeline (19 rows x 512 s per stage).
// feats: streamed directly via LDG.128 with a 1-step register double buffer
// (fv current / fw next) so the 4 independent DRAM loads are always in
// flight one step ahead — including across the chunk barrier.
// Register tile: 19 k x 4 c f32x2 accumulators.
// ---------------------------------------------------------------------------
__device__ __forceinline__ void fma2(unsigned long long& acc,
                                     unsigned long long a,
                                     unsigned long long b) {
    asm("fma.rn.f32x2 %0, %1, %2, %3;" : "=l"(acc) : "l"(a), "l"(b), "l"(acc));
}
#define CP_ASYNC16(dst, src) \
    asm volatile("cp.async.cg.shared.global [%0], [%1], 16;\n" :: "r"(dst), "l"(src))

__global__ void __launch_bounds__(256, 1) gather_kernel(const float* __restrict__ feats) {
    extern __shared__ float sm[];
    const int b    = blockIdx.y;
    const int z    = blockIdx.z;
    const int tid  = threadIdx.x;
    const int warp = tid >> 5;
    const int lane = tid & 31;
    const int cbase = blockIdx.x * CT;

    // ---- probs fill bases (constant stride per thread) ----
    // 2432 16B tiles per chunk; thread t covers tiles t + 256j:
    // row = (t>>7) + 2j, col = (t&127)*4 floats. tid<128 -> 10 tiles, else 9.
    const char* psrc = (const char*)(g_probs + (size_t)b * K * S + (size_t)z * SPB
                                     + (size_t)(tid >> 7) * S) + (tid & 127) * 16;
    const unsigned sbase = (unsigned)__cvta_generic_to_shared(sm);
    const unsigned pdst = sbase + (unsigned)((tid >> 7) * (CHUNK * 4) + (tid & 127) * 16);
    const bool p_extra = (tid < 128);

    auto fill = [&](int chunk, int stage) {
        const char* ps = psrc + chunk * (CHUNK * 4);
        const unsigned pd = pdst + stage * PROB_BYTES;
        #pragma unroll
        for (int j = 0; j < 9; ++j)
            CP_ASYNC16(pd + j * (2 * CHUNK * 4), ps + (size_t)j * (2 * S * 4));
        if (p_extra)
            CP_ASYNC16(pd + 9 * (2 * CHUNK * 4), ps + (size_t)9 * (2 * S * 4));
    };

    // ---- feats stream bases: 4 rows per warp ----
    const float* __restrict__ fg = feats + (size_t)(b * C + cbase + warp * 4) * S
                                 + (size_t)z * SPB + lane * 4;

    unsigned long long acc[K][4];
    #pragma unroll
    for (int k = 0; k < K; ++k)
        #pragma unroll
        for (int j = 0; j < 4; ++j) acc[k][j] = 0ULL;

    // Prologue: probs chunk 0 in flight; feats step 0 of chunk 0 in regs.
    fill(0, 0);
    asm volatile("cp.async.commit_group;\n");

    ulonglong2 fv0 = *(const ulonglong2*)(fg + 0 * S);
    ulonglong2 fv1 = *(const ulonglong2*)(fg + 1 * S);
    ulonglong2 fv2 = *(const ulonglong2*)(fg + 2 * S);
    ulonglong2 fv3 = *(const ulonglong2*)(fg + 3 * S);

    #pragma unroll 1
    for (int it = 0; it < CPB; ++it) {
        asm volatile("cp.async.wait_group 0;\n");
        __syncthreads();   // probs chunk `it` visible; other stage free

        if (it + 1 < CPB) fill(it + 1, (it + 1) & 1);
        asm volatile("cp.async.commit_group;\n");

        const float* sb = sm + (it & 1) * PROB_FLOATS;
        #pragma unroll
        for (int step = 0; step < CHUNK / 128; ++step) {
            // prefetch next step's feats (or next chunk's step 0)
            const int nxt = it * CHUNK + (step + 1) * 128;
            ulonglong2 fw0, fw1, fw2, fw3;
            if (nxt < SPB) {
                fw0 = *(const ulonglong2*)(fg + 0 * S + nxt);
                fw1 = *(const ulonglong2*)(fg + 1 * S + nxt);
                fw2 = *(const ulonglong2*)(fg + 2 * S + nxt);
                fw3 = *(const ulonglong2*)(fg + 3 * S + nxt);
            }
            const int s0 = step * 128 + lane * 4;
            #pragma unroll
            for (int k = 0; k < K; ++k) {
                ulonglong2 pv = *(const ulonglong2*)(sb + k * CHUNK + s0);
                fma2(acc[k][0], pv.x, fv0.x);
                fma2(acc[k][1], pv.x, fv1.x);
                fma2(acc[k][2], pv.x, fv2.x);
                fma2(acc[k][3], pv.x, fv3.x);
                fma2(acc[k][0], pv.y, fv0.y);
                fma2(acc[k][1], pv.y, fv1.y);
                fma2(acc[k][2], pv.y, fv2.y);
                fma2(acc[k][3], pv.y, fv3.y);
            }
            if (nxt < SPB) {
                fv0 = fw0; fv1 = fw1; fv2 = fw2; fv3 = fw3;
            }
        }
    }

    // Epilogue: pair-add, warp butterfly reduce, write PARTIAL (no invsum).
    #pragma unroll
    for (int k = 0; k < K; ++k) {
        #pragma unroll
        for (int j = 0; j < 4; ++j) {
            float2 v = *(float2*)&acc[k][j];
            float s = v.x + v.y;
            s += __shfl_xor_sync(0xffffffffu, s, 16);
            s += __shfl_xor_sync(0xffffffffu, s, 8);
            s += __shfl_xor_sync(0xffffffffu, s, 4);
            s += __shfl_xor_sync(0xffffffffu, s, 2);
            s += __shfl_xor_sync(0xffffffffu, s, 1);
            if (lane == ((k * 4 + j) & 31))
                g_part[z][(size_t)(b * C + cbase + warp * 4 + j) * K + k] = s;
        }
    }
}

// ---------------------------------------------------------------------------
// Kernel 3: sum z-partials, apply invsum, write final out[b][c][k].
// ---------------------------------------------------------------------------
__global__ void __launch_bounds__(256) reduce_kernel(float* __restrict__ out) {
    const int i = blockIdx.x * 256 + threadIdx.x;
    if (i >= B * C * K) return;
    float s = 0.f;
    #pragma unroll
    for (int zz = 0; zz < ZSPLIT; ++zz) s += g_part[zz][i];
    const int k = i % K;
    const int b = i / (C * K);
    out[i] = s * g_invsum[b * K + k];
}

// ---------------------------------------------------------------------------
extern "C" void kernel_launch(void* const* d_in, const int* in_sizes, int n_in,
                              void* d_out, int out_size) {
    const float* feats = (const float*)d_in[0];  // [8,512,128,128]
    const float* aux   = (const float*)d_in[1];  // [8,19,128,128]
    float* out = (float*)d_out;                  // [8,512,19,1]

    cudaFuncSetAttribute(gather_kernel,
                         cudaFuncAttributeMaxDynamicSharedMemorySize, SMEM_BYTES);

    softmax_stats_kernel<<<B * K, 512>>>(aux);
    dim3 grid(C / CT, B, ZSPLIT);
    gather_kernel<<<grid, 256, SMEM_BYTES>>>(feats);
    reduce_kernel<<<(B * C * K + 255) / 256, 256>>>(out);
}

// round 8
// speedup vs baseline: 1.1500x; 1.1500x over previous
#include <cuda_runtime.h>
#include <cuda_fp16.h>
#include <cstdint>

#define B 8
#define K 19
#define C 512
#define S 16384

#define CT     32                      // channels per block
#define CHUNK  512                     // s per pipeline stage
#define ZSPLIT 8                       // s-range split across blocks
#define SPB    (S / ZSPLIT)            // 2048
#define CPB    (SPB / CHUNK)           // 4 chunks per block
#define FEAT_BYTES (CT * CHUNK * 4)    // 65536
#define PROB_BYTES (K * CHUNK * 2)     // 19456 (fp16)
#define STAGE_BYTES (FEAT_BYTES + PROB_BYTES)  // 84992
#define SMEM_BYTES  (2 * STAGE_BYTES)          // 169984

// Scratch: probs stored as fp16 (10 mantissa bits: rel_err ~2e-4, halves
// probs STS/LDS/DRAM traffic vs fp32).
__device__ __half g_probs[B * K * S];
__device__ float g_invsum[B * K];
__device__ float g_part[ZSPLIT][B * C * K];

// ---------------------------------------------------------------------------
// Kernel 1: per-(b,k) row: rowmax, e = exp(x-max) -> g_probs (fp16), 1/sum.
// invsum is computed from the fp16-ROUNDED weights so numerator and
// denominator use identical weights (cancels common-mode rounding bias).
// ---------------------------------------------------------------------------
__global__ void __launch_bounds__(512) softmax_stats_kernel(const float* __restrict__ aux) {
    const int row = blockIdx.x;
    const float4* __restrict__ src = (const float4*)(aux + (size_t)row * S);
    uint2* __restrict__ dst = (uint2*)(g_probs + (size_t)row * S);
    const int tid = threadIdx.x;
    __shared__ float sred[16];
    __shared__ float smax;

    float m = -1e30f;
    #pragma unroll 4
    for (int i = tid; i < S / 4; i += 512) {
        float4 v = src[i];
        m = fmaxf(m, fmaxf(fmaxf(v.x, v.y), fmaxf(v.z, v.w)));
    }
    #pragma unroll
    for (int o = 16; o; o >>= 1) m = fmaxf(m, __shfl_xor_sync(0xffffffffu, m, o));
    if ((tid & 31) == 0) sred[tid >> 5] = m;
    __syncthreads();
    if (tid == 0) {
        float v = sred[0];
        #pragma unroll
        for (int w = 1; w < 16; ++w) v = fmaxf(v, sred[w]);
        smax = v;
    }
    __syncthreads();
    const float mx = smax;

    float sum = 0.f;
    #pragma unroll 4
    for (int i = tid; i < S / 4; i += 512) {
        float4 v = src[i];
        __half2 h01 = __floats2half2_rn(__expf(v.x - mx), __expf(v.y - mx));
        __half2 h23 = __floats2half2_rn(__expf(v.z - mx), __expf(v.w - mx));
        uint2 w;
        w.x = *(uint32_t*)&h01;
        w.y = *(uint32_t*)&h23;
        dst[i] = w;
        float2 r01 = __half22float2(h01);
        float2 r23 = __half22float2(h23);
        sum += (r01.x + r01.y) + (r23.x + r23.y);
    }
    #pragma unroll
    for (int o = 16; o; o >>= 1) sum += __shfl_xor_sync(0xffffffffu, sum, o);
    if ((tid & 31) == 0) sred[tid >> 5] = sum;
    __syncthreads();
    if (tid == 0) {
        float t = 0.f;
        #pragma unroll
        for (int w = 0; w < 16; ++w) t += sred[w];
        g_invsum[row] = 1.0f / t;
    }
}

// ---------------------------------------------------------------------------
// Kernel 2: partial ctx over this block's s-range.
// cp.async 2-stage pipeline; feats fp32 rows + probs fp16 rows per stage.
// Register tile: 19 k x 4 c f32x2 accumulators; fp16->fp32 cvt on alu pipe.
// ---------------------------------------------------------------------------
__device__ __forceinline__ void fma2(unsigned long long& acc,
                                     unsigned long long a,
                                     unsigned long long b) {
    asm("fma.rn.f32x2 %0, %1, %2, %3;" : "=l"(acc) : "l"(a), "l"(b), "l"(acc));
}
#define CP_ASYNC16(dst, src) \
    asm volatile("cp.async.cg.shared.global [%0], [%1], 16;\n" :: "r"(dst), "l"(src))

__global__ void __launch_bounds__(256, 1) gather_kernel(const float* __restrict__ feats) {
    extern __shared__ char sm[];
    const int b    = blockIdx.y;
    const int z    = blockIdx.z;
    const int tid  = threadIdx.x;
    const int warp = tid >> 5;
    const int lane = tid & 31;
    const int cbase = blockIdx.x * CT;

    // ---- fill bases (constant stride per thread) ----
    // feats: 4096 16B tiles/chunk; thread t: rows (t>>7)+2j, col (t&127)*16B, j=0..15
    const char* fsrc = (const char*)(feats + (size_t)(b * C + cbase) * S + (size_t)z * SPB)
                       + (size_t)(tid >> 7) * (S * 4) + (tid & 127) * 16;
    // probs(fp16): 1216 16B tiles/chunk; thread t: rows (t>>6)+4j, col (t&63)*16B,
    // j=0..3 all threads, j=4 for t<192 (rows 16..18)
    const char* psrc = (const char*)(g_probs + (size_t)b * K * S + (size_t)z * SPB)
                       + (size_t)(tid >> 6) * (S * 2) + (tid & 63) * 16;
    const unsigned sbase = (unsigned)__cvta_generic_to_shared(sm);
    const unsigned fdst = sbase + (unsigned)((tid >> 7) * (CHUNK * 4) + (tid & 127) * 16);
    const unsigned pdst = sbase + FEAT_BYTES
                        + (unsigned)((tid >> 6) * (CHUNK * 2) + (tid & 63) * 16);
    const bool p_extra = (tid < 192);

    auto fill = [&](int chunk, int stage) {
        const char* fs = fsrc + chunk * (CHUNK * 4);
        const char* ps = psrc + chunk * (CHUNK * 2);
        const unsigned fd = fdst + stage * STAGE_BYTES;
        const unsigned pd = pdst + stage * STAGE_BYTES;
        #pragma unroll
        for (int j = 0; j < 16; ++j)
            CP_ASYNC16(fd + j * (2 * CHUNK * 4), fs + (size_t)j * (2 * S * 4));
        #pragma unroll
        for (int j = 0; j < 4; ++j)
            CP_ASYNC16(pd + j * (4 * CHUNK * 2), ps + (size_t)j * (4 * S * 2));
        if (p_extra)
            CP_ASYNC16(pd + 4 * (4 * CHUNK * 2), ps + (size_t)4 * (4 * S * 2));
    };

    unsigned long long acc[K][4];
    #pragma unroll
    for (int k = 0; k < K; ++k)
        #pragma unroll
        for (int j = 0; j < 4; ++j) acc[k][j] = 0ULL;

    fill(0, 0);
    asm volatile("cp.async.commit_group;\n");

    #pragma unroll 1
    for (int it = 0; it < CPB; ++it) {
        asm volatile("cp.async.wait_group 0;\n");
        __syncthreads();   // chunk `it` visible; other stage free to refill

        if (it + 1 < CPB) fill(it + 1, (it + 1) & 1);
        asm volatile("cp.async.commit_group;\n");

        const char* sb = sm + (it & 1) * STAGE_BYTES;
        const float* fb = (const float*)sb;
        const char* pb = sb + FEAT_BYTES;
        #pragma unroll
        for (int step = 0; step < CHUNK / 128; ++step) {
            const int s0 = step * 128 + lane * 4;
            const ulonglong2 fv0 = *(const ulonglong2*)(fb + (warp * 4 + 0) * CHUNK + s0);
            const ulonglong2 fv1 = *(const ulonglong2*)(fb + (warp * 4 + 1) * CHUNK + s0);
            const ulonglong2 fv2 = *(const ulonglong2*)(fb + (warp * 4 + 2) * CHUNK + s0);
            const ulonglong2 fv3 = *(const ulonglong2*)(fb + (warp * 4 + 3) * CHUNK + s0);
            #pragma unroll
            for (int k = 0; k < K; ++k) {
                const uint2 pu = *(const uint2*)(pb + k * (CHUNK * 2) + s0 * 2);
                const float2 f01 = __half22float2(*(const __half2*)&pu.x);
                const float2 f23 = __half22float2(*(const __half2*)&pu.y);
                unsigned long long pa, pc;
                asm("mov.b64 %0, {%1, %2};" : "=l"(pa) : "f"(f01.x), "f"(f01.y));
                asm("mov.b64 %0, {%1, %2};" : "=l"(pc) : "f"(f23.x), "f"(f23.y));
                fma2(acc[k][0], pa, fv0.x);
                fma2(acc[k][1], pa, fv1.x);
                fma2(acc[k][2], pa, fv2.x);
                fma2(acc[k][3], pa, fv3.x);
                fma2(acc[k][0], pc, fv0.y);
                fma2(acc[k][1], pc, fv1.y);
                fma2(acc[k][2], pc, fv2.y);
                fma2(acc[k][3], pc, fv3.y);
            }
        }
    }

    // Epilogue: pair-add, warp butterfly reduce, write PARTIAL (no invsum).
    #pragma unroll
    for (int k = 0; k < K; ++k) {
        #pragma unroll
        for (int j = 0; j < 4; ++j) {
            float2 v = *(float2*)&acc[k][j];
            float s = v.x + v.y;
            s += __shfl_xor_sync(0xffffffffu, s, 16);
            s += __shfl_xor_sync(0xffffffffu, s, 8);
            s += __shfl_xor_sync(0xffffffffu, s, 4);
            s += __shfl_xor_sync(0xffffffffu, s, 2);
            s += __shfl_xor_sync(0xffffffffu, s, 1);
            if (lane == ((k * 4 + j) & 31))
                g_part[z][(size_t)(b * C + cbase + warp * 4 + j) * K + k] = s;
        }
    }
}

// ---------------------------------------------------------------------------
// Kernel 3: sum z-partials, apply invsum, write final out[b][c][k].
// ---------------------------------------------------------------------------
__global__ void __launch_bounds__(256) reduce_kernel(float* __restrict__ out) {
    const int i = blockIdx.x * 256 + threadIdx.x;
    if (i >= B * C * K) return;
    float s = 0.f;
    #pragma unroll
    for (int zz = 0; zz < ZSPLIT; ++zz) s += g_part[zz][i];
    const int k = i % K;
    const int b = i / (C * K);
    out[i] = s * g_invsum[b * K + k];
}

// ---------------------------------------------------------------------------
extern "C" void kernel_launch(void* const* d_in, const int* in_sizes, int n_in,
                              void* d_out, int out_size) {
    const float* feats = (const float*)d_in[0];  // [8,512,128,128]
    const float* aux   = (const float*)d_in[1];  // [8,19,128,128]
    float* out = (float*)d_out;                  // [8,512,19,1]

    cudaFuncSetAttribute(gather_kernel,
                         cudaFuncAttributeMaxDynamicSharedMemorySize, SMEM_BYTES);

    softmax_stats_kernel<<<B * K, 512>>>(aux);
    dim3 grid(C / CT, B, ZSPLIT);
    gather_kernel<<<grid, 256, SMEM_BYTES>>>(feats);
    reduce_kernel<<<(B * C * K + 255) / 256, 256>>>(out);
}

// round 9
// speedup vs baseline: 1.1680x; 1.0156x over previous
#include <cuda_runtime.h>
#include <cstdint>

#define B 8
#define K 19
#define C 512
#define S 16384

#define CT     32                      // channels per block
#define CHUNK  512                     // s per pipeline stage
#define ZSPLIT 8                       // s-range split across blocks
#define SPB    (S / ZSPLIT)            // 2048
#define CPB    (SPB / CHUNK)           // 4 chunks per block
#define FEAT_FLOATS (CT * CHUNK)       // 16384
#define PROB_FLOATS (K * CHUNK)        // 9728
#define STAGE_FLOATS (FEAT_FLOATS + PROB_FLOATS)   // 26112
#define STAGE_BYTES  (STAGE_FLOATS * 4)            // 104448
#define SMEM_BYTES   (2 * STAGE_BYTES)             // 208896

// Scratch (fp32 everywhere — R8 lesson: no cvt in the FMA loop)
__device__ float g_probs[B * K * S];
__device__ float g_invsum[B * K];
__device__ float g_part[ZSPLIT][B * C * K];

// ---------------------------------------------------------------------------
// Kernel 1: per-(b,k) row: rowmax, e = exp(x - max) -> g_probs, 1/sum(e).
// ---------------------------------------------------------------------------
__global__ void __launch_bounds__(512) softmax_stats_kernel(const float* __restrict__ aux) {
    const int row = blockIdx.x;
    const float4* __restrict__ src = (const float4*)(aux + (size_t)row * S);
    float4* __restrict__ dst = (float4*)(g_probs + (size_t)row * S);
    const int tid = threadIdx.x;
    __shared__ float sred[16];
    __shared__ float smax;

    float m = -1e30f;
    #pragma unroll 4
    for (int i = tid; i < S / 4; i += 512) {
        float4 v = src[i];
        m = fmaxf(m, fmaxf(fmaxf(v.x, v.y), fmaxf(v.z, v.w)));
    }
    #pragma unroll
    for (int o = 16; o; o >>= 1) m = fmaxf(m, __shfl_xor_sync(0xffffffffu, m, o));
    if ((tid & 31) == 0) sred[tid >> 5] = m;
    __syncthreads();
    if (tid == 0) {
        float v = sred[0];
        #pragma unroll
        for (int w = 1; w < 16; ++w) v = fmaxf(v, sred[w]);
        smax = v;
    }
    __syncthreads();
    const float mx = smax;

    float sum = 0.f;
    #pragma unroll 4
    for (int i = tid; i < S / 4; i += 512) {
        float4 v = src[i];
        float4 e;
        e.x = __expf(v.x - mx);
        e.y = __expf(v.y - mx);
        e.z = __expf(v.z - mx);
        e.w = __expf(v.w - mx);
        dst[i] = e;
        sum += (e.x + e.y) + (e.z + e.w);
    }
    #pragma unroll
    for (int o = 16; o; o >>= 1) sum += __shfl_xor_sync(0xffffffffu, sum, o);
    if ((tid & 31) == 0) sred[tid >> 5] = sum;
    __syncthreads();
    if (tid == 0) {
        float t = 0.f;
        #pragma unroll
        for (int w = 0; w < 16; ++w) t += sred[w];
        g_invsum[row] = 1.0f / t;
    }
}

// ---------------------------------------------------------------------------
// Kernel 2: partial ctx over this block's s-range.
// k-split warp layout: warp w -> kgroup = w>>2 (k=0..9 / k=10..18, row 10 of
// group B is a clamped duplicate of row 18, computed but never stored) and
// cgroup = w&3 (8 channels each). This halves probs smem re-reads (the R4
// crossbar binder). cp.async 2-stage pipeline, CHUNK=512, LDS.64 sub-steps.
// ---------------------------------------------------------------------------
__device__ __forceinline__ void fma2(unsigned long long& acc,
                                     unsigned long long a,
                                     unsigned long long b) {
    asm("fma.rn.f32x2 %0, %1, %2, %3;" : "=l"(acc) : "l"(a), "l"(b), "l"(acc));
}
#define CP_ASYNC16(dst, src) \
    asm volatile("cp.async.cg.shared.global [%0], [%1], 16;\n" :: "r"(dst), "l"(src))

__global__ void __launch_bounds__(256, 1) gather_kernel(const float* __restrict__ feats) {
    extern __shared__ float sm[];
    const int b    = blockIdx.y;
    const int z    = blockIdx.z;
    const int tid  = threadIdx.x;
    const int warp = tid >> 5;
    const int lane = tid & 31;
    const int cbase = blockIdx.x * CT;
    const int kg   = warp >> 2;          // 0: k0..9, 1: k10..18(+dup)
    const int cg   = warp & 3;           // 8 channels each
    const int k0   = kg * 10;

    // ---- fill bases (R4-proven constant-stride scheme) ----
    const char* fsrc = (const char*)(feats + (size_t)(b * C + cbase) * S + (size_t)z * SPB)
                       + (size_t)(tid >> 7) * (S * 4) + (tid & 127) * 16;
    const char* psrc = (const char*)(g_probs + (size_t)b * K * S + (size_t)z * SPB)
                       + (size_t)(tid >> 7) * (S * 4) + (tid & 127) * 16;
    const unsigned sbase = (unsigned)__cvta_generic_to_shared(sm);
    const unsigned fdst = sbase + (unsigned)((tid >> 7) * (CHUNK * 4) + (tid & 127) * 16);
    const unsigned pdst = fdst + FEAT_FLOATS * 4;
    const bool p_extra = (tid < 128);    // probs tile j==9 (rows 18)

    auto fill = [&](int chunk, int stage) {
        const char* fs = fsrc + chunk * (CHUNK * 4);
        const char* ps = psrc + chunk * (CHUNK * 4);
        const unsigned fd = fdst + stage * STAGE_BYTES;
        const unsigned pd = pdst + stage * STAGE_BYTES;
        #pragma unroll
        for (int j = 0; j < 16; ++j)
            CP_ASYNC16(fd + j * (2 * CHUNK * 4), fs + (size_t)j * (2 * S * 4));
        #pragma unroll
        for (int j = 0; j < 9; ++j)
            CP_ASYNC16(pd + j * (2 * CHUNK * 4), ps + (size_t)j * (2 * S * 4));
        if (p_extra)
            CP_ASYNC16(pd + 9 * (2 * CHUNK * 4), ps + (size_t)9 * (2 * S * 4));
    };

    // probs row offsets for this warp's 10 k rows (clamped at 18)
    int prow[10];
    #pragma unroll
    for (int kk = 0; kk < 10; ++kk) {
        int k = k0 + kk;
        prow[kk] = (k > 18 ? 18 : k) * CHUNK;
    }

    unsigned long long acc[10][8];
    #pragma unroll
    for (int kk = 0; kk < 10; ++kk)
        #pragma unroll
        for (int j = 0; j < 8; ++j) acc[kk][j] = 0ULL;

    fill(0, 0);
    asm volatile("cp.async.commit_group;\n");

    #pragma unroll 1
    for (int it = 0; it < CPB; ++it) {
        asm volatile("cp.async.wait_group 0;\n");
        __syncthreads();   // chunk `it` visible; other stage free to refill

        if (it + 1 < CPB) fill(it + 1, (it + 1) & 1);
        asm volatile("cp.async.commit_group;\n");

        const float* fb = sm + (it & 1) * STAGE_FLOATS + cg * (8 * CHUNK);
        const float* pb = sm + (it & 1) * STAGE_FLOATS + FEAT_FLOATS;
        #pragma unroll 2
        for (int sub = 0; sub < 8; ++sub) {
            const int s0 = sub * 64 + lane * 2;
            unsigned long long fv[8];
            #pragma unroll
            for (int j = 0; j < 8; ++j)
                fv[j] = *(const unsigned long long*)(fb + j * CHUNK + s0);
            #pragma unroll
            for (int kk = 0; kk < 10; ++kk) {
                const unsigned long long pv =
                    *(const unsigned long long*)(pb + prow[kk] + s0);
                fma2(acc[kk][0], pv, fv[0]);
                fma2(acc[kk][1], pv, fv[1]);
                fma2(acc[kk][2], pv, fv[2]);
                fma2(acc[kk][3], pv, fv[3]);
                fma2(acc[kk][4], pv, fv[4]);
                fma2(acc[kk][5], pv, fv[5]);
                fma2(acc[kk][6], pv, fv[6]);
                fma2(acc[kk][7], pv, fv[7]);
            }
        }
    }

    // Epilogue: pair-add, butterfly reduce, store PARTIALS (skip dup row).
    #pragma unroll
    for (int kk = 0; kk < 10; ++kk) {
        const int k = k0 + kk;
        if (k < K) {
            #pragma unroll
            for (int j = 0; j < 8; ++j) {
                float2 v = *(float2*)&acc[kk][j];
                float s = v.x + v.y;
                s += __shfl_xor_sync(0xffffffffu, s, 16);
                s += __shfl_xor_sync(0xffffffffu, s, 8);
                s += __shfl_xor_sync(0xffffffffu, s, 4);
                s += __shfl_xor_sync(0xffffffffu, s, 2);
                s += __shfl_xor_sync(0xffffffffu, s, 1);
                if (lane == ((kk * 8 + j) & 31))
                    g_part[z][(size_t)(b * C + cbase + cg * 8 + j) * K + k] = s;
            }
        }
    }
}

// ---------------------------------------------------------------------------
// Kernel 3: sum z-partials, apply invsum, write final out[b][c][k].
// ---------------------------------------------------------------------------
__global__ void __launch_bounds__(256) reduce_kernel(float* __restrict__ out) {
    const int i = blockIdx.x * 256 + threadIdx.x;
    if (i >= B * C * K) return;
    float s = 0.f;
    #pragma unroll
    for (int zz = 0; zz < ZSPLIT; ++zz) s += g_part[zz][i];
    const int k = i % K;
    const int b = i / (C * K);
    out[i] = s * g_invsum[b * K + k];
}

// ---------------------------------------------------------------------------
extern "C" void kernel_launch(void* const* d_in, const int* in_sizes, int n_in,
                              void* d_out, int out_size) {
    const float* feats = (const float*)d_in[0];  // [8,512,128,128]
    const float* aux   = (const float*)d_in[1];  // [8,19,128,128]
    float* out = (float*)d_out;                  // [8,512,19,1]

    cudaFuncSetAttribute(gather_kernel,
                         cudaFuncAttributeMaxDynamicSharedMemorySize, SMEM_BYTES);

    softmax_stats_kernel<<<B * K, 512>>>(aux);
    dim3 grid(C / CT, B, ZSPLIT);
    gather_kernel<<<grid, 256, SMEM_BYTES>>>(feats);
    reduce_kernel<<<(B * C * K + 255) / 256, 256>>>(out);
}

// round 11
// speedup vs baseline: 1.2150x; 1.0403x over previous
#include <cuda_runtime.h>
#include <cstdint>

#define B 8
#define K 19
#define C 512
#define S 16384

#define CT     32                      // channels per block
#define CHUNK  256                     // s per pipeline stage
#define STAGES 4
#define ZSPLIT 8                       // s-range split across blocks
#define SPB    (S / ZSPLIT)            // 2048
#define CPB    (SPB / CHUNK)           // 8 chunks per block
#define FEAT_FLOATS (CT * CHUNK)       // 8192
#define PROB_FLOATS (K * CHUNK)        // 4864
#define STAGE_FLOATS (FEAT_FLOATS + PROB_FLOATS)   // 13056
#define STAGE_BYTES  (STAGE_FLOATS * 4)            // 52224
#define SMEM_BYTES   (STAGES * STAGE_BYTES)        // 208896

// Scratch (fp32 everywhere)
__device__ float g_probs[B * K * S];
__device__ float g_invsum[B * K];
__device__ float g_part[ZSPLIT][B * C * K];

// ---------------------------------------------------------------------------
// Kernel 1: per-(b,k) row: rowmax, e = exp(x - max) -> g_probs, 1/sum(e).
// ---------------------------------------------------------------------------
__global__ void __launch_bounds__(512) softmax_stats_kernel(const float* __restrict__ aux) {
    const int row = blockIdx.x;
    const float4* __restrict__ src = (const float4*)(aux + (size_t)row * S);
    float4* __restrict__ dst = (float4*)(g_probs + (size_t)row * S);
    const int tid = threadIdx.x;
    __shared__ float sred[16];
    __shared__ float smax;

    float m = -1e30f;
    #pragma unroll 4
    for (int i = tid; i < S / 4; i += 512) {
        float4 v = src[i];
        m = fmaxf(m, fmaxf(fmaxf(v.x, v.y), fmaxf(v.z, v.w)));
    }
    #pragma unroll
    for (int o = 16; o; o >>= 1) m = fmaxf(m, __shfl_xor_sync(0xffffffffu, m, o));
    if ((tid & 31) == 0) sred[tid >> 5] = m;
    __syncthreads();
    if (tid == 0) {
        float v = sred[0];
        #pragma unroll
        for (int w = 1; w < 16; ++w) v = fmaxf(v, sred[w]);
        smax = v;
    }
    __syncthreads();
    const float mx = smax;

    float sum = 0.f;
    #pragma unroll 4
    for (int i = tid; i < S / 4; i += 512) {
        float4 v = src[i];
        float4 e;
        e.x = __expf(v.x - mx);
        e.y = __expf(v.y - mx);
        e.z = __expf(v.z - mx);
        e.w = __expf(v.w - mx);
        dst[i] = e;
        sum += (e.x + e.y) + (e.z + e.w);
    }
    #pragma unroll
    for (int o = 16; o; o >>= 1) sum += __shfl_xor_sync(0xffffffffu, sum, o);
    if ((tid & 31) == 0) sred[tid >> 5] = sum;
    __syncthreads();
    if (tid == 0) {
        float t = 0.f;
        #pragma unroll
        for (int w = 0; w < 16; ++w) t += sred[w];
        g_invsum[row] = 1.0f / t;
    }
}

// ---------------------------------------------------------------------------
// Kernel 2: partial ctx over this block's s-range. (Re-run of R10 config —
// prior attempt failed in infra before executing.)
// R4 compute layout (19k x 4c f32x2 acc, LDS.128, 8 warps) with a DEEP
// cp.async ring: 4 stages of CHUNK=256, wait_group 2 -> fills issued 3
// chunk-periods ahead (~156 KB in flight/SM) so DRAM latency/jitter never
// reaches the barrier. Z=8 for wave-fit (1024 blocks = 6.92 waves).
// ---------------------------------------------------------------------------
__device__ __forceinline__ void fma2(unsigned long long& acc,
                                     unsigned long long a,
                                     unsigned long long b) {
    asm("fma.rn.f32x2 %0, %1, %2, %3;" : "=l"(acc) : "l"(a), "l"(b), "l"(acc));
}
#define CP_ASYNC16(dst, src) \
    asm volatile("cp.async.cg.shared.global [%0], [%1], 16;\n" :: "r"(dst), "l"(src))

__global__ void __launch_bounds__(256, 1) gather_kernel(const float* __restrict__ feats) {
    extern __shared__ float sm[];
    const int b    = blockIdx.y;
    const int z    = blockIdx.z;
    const int tid  = threadIdx.x;
    const int warp = tid >> 5;
    const int lane = tid & 31;
    const int cbase = blockIdx.x * CT;

    // ---- fill bases (constant stride per thread) ----
    // CHUNK=256 -> 64 16B tiles per row. Thread t: base row t>>6 (0..3),
    // col (t&63)*16B; j advances 4 rows (gmem stride 4*S*4 B, smem 4*CHUNK*4 B).
    // feats: j=0..7 (32 rows). probs: j=0..3 (16 rows) + j=4 rows 16..18 (t<192).
    const char* fsrc = (const char*)(feats + (size_t)(b * C + cbase) * S + (size_t)z * SPB)
                       + (size_t)(tid >> 6) * (S * 4) + (tid & 63) * 16;
    const char* psrc = (const char*)(g_probs + (size_t)b * K * S + (size_t)z * SPB)
                       + (size_t)(tid >> 6) * (S * 4) + (tid & 63) * 16;
    const unsigned sbase = (unsigned)__cvta_generic_to_shared(sm);
    const unsigned fdst = sbase + (unsigned)((tid >> 6) * (CHUNK * 4) + (tid & 63) * 16);
    const unsigned pdst = fdst + FEAT_FLOATS * 4;
    const bool p_extra = (tid < 192);    // probs rows 16..18

    auto fill = [&](int chunk, int stage) {
        const char* fs = fsrc + chunk * (CHUNK * 4);
        const char* ps = psrc + chunk * (CHUNK * 4);
        const unsigned fd = fdst + stage * STAGE_BYTES;
        const unsigned pd = pdst + stage * STAGE_BYTES;
        #pragma unroll
        for (int j = 0; j < 8; ++j)
            CP_ASYNC16(fd + j * (4 * CHUNK * 4), fs + (size_t)j * (4 * S * 4));
        #pragma unroll
        for (int j = 0; j < 4; ++j)
            CP_ASYNC16(pd + j * (4 * CHUNK * 4), ps + (size_t)j * (4 * S * 4));
        if (p_extra)
            CP_ASYNC16(pd + 4 * (4 * CHUNK * 4), ps + (size_t)4 * (4 * S * 4));
    };

    unsigned long long acc[K][4];
    #pragma unroll
    for (int k = 0; k < K; ++k)
        #pragma unroll
        for (int j = 0; j < 4; ++j) acc[k][j] = 0ULL;

    // Prologue: 3 chunks in flight.
    fill(0, 0);
    asm volatile("cp.async.commit_group;\n");
    fill(1, 1);
    asm volatile("cp.async.commit_group;\n");
    fill(2, 2);
    asm volatile("cp.async.commit_group;\n");

    #pragma unroll 1
    for (int it = 0; it < CPB; ++it) {
        // chunk `it` complete when <=2 groups outstanding (it+1, it+2)
        asm volatile("cp.async.wait_group 2;\n");
        __syncthreads();   // visibility + stage (it-1)%4 reuse safety

        if (it + 3 < CPB) fill(it + 3, (it + 3) & 3);
        asm volatile("cp.async.commit_group;\n");

        const float* sb = sm + (it & 3) * STAGE_FLOATS;
        #pragma unroll
        for (int step = 0; step < CHUNK / 128; ++step) {
            const int s0 = step * 128 + lane * 4;
            const ulonglong2 fv0 = *(const ulonglong2*)(sb + (warp * 4 + 0) * CHUNK + s0);
            const ulonglong2 fv1 = *(const ulonglong2*)(sb + (warp * 4 + 1) * CHUNK + s0);
            const ulonglong2 fv2 = *(const ulonglong2*)(sb + (warp * 4 + 2) * CHUNK + s0);
            const ulonglong2 fv3 = *(const ulonglong2*)(sb + (warp * 4 + 3) * CHUNK + s0);
            #pragma unroll
            for (int k = 0; k < K; ++k) {
                ulonglong2 pv = *(const ulonglong2*)(sb + FEAT_FLOATS + k * CHUNK + s0);
                fma2(acc[k][0], pv.x, fv0.x);
                fma2(acc[k][1], pv.x, fv1.x);
                fma2(acc[k][2], pv.x, fv2.x);
                fma2(acc[k][3], pv.x, fv3.x);
                fma2(acc[k][0], pv.y, fv0.y);
                fma2(acc[k][1], pv.y, fv1.y);
                fma2(acc[k][2], pv.y, fv2.y);
                fma2(acc[k][3], pv.y, fv3.y);
            }
        }
    }

    // Epilogue: pair-add, warp butterfly reduce, write PARTIAL (no invsum).
    #pragma unroll
    for (int k = 0; k < K; ++k) {
        #pragma unroll
        for (int j = 0; j < 4; ++j) {
            float2 v = *(float2*)&acc[k][j];
            float s = v.x + v.y;
            s += __shfl_xor_sync(0xffffffffu, s, 16);
            s += __shfl_xor_sync(0xffffffffu, s, 8);
            s += __shfl_xor_sync(0xffffffffu, s, 4);
            s += __shfl_xor_sync(0xffffffffu, s, 2);
            s += __shfl_xor_sync(0xffffffffu, s, 1);
            if (lane == ((k * 4 + j) & 31))
                g_part[z][(size_t)(b * C + cbase + warp * 4 + j) * K + k] = s;
        }
    }
}

// ---------------------------------------------------------------------------
// Kernel 3: sum z-partials, apply invsum, write final out[b][c][k].
// ---------------------------------------------------------------------------
__global__ void __launch_bounds__(256) reduce_kernel(float* __restrict__ out) {
    const int i = blockIdx.x * 256 + threadIdx.x;
    if (i >= B * C * K) return;
    float s = 0.f;
    #pragma unroll
    for (int zz = 0; zz < ZSPLIT; ++zz) s += g_part[zz][i];
    const int k = i % K;
    const int b = i / (C * K);
    out[i] = s * g_invsum[b * K + k];
}

// ---------------------------------------------------------------------------
extern "C" void kernel_launch(void* const* d_in, const int* in_sizes, int n_in,
                              void* d_out, int out_size) {
    const float* feats = (const float*)d_in[0];  // [8,512,128,128]
    const float* aux   = (const float*)d_in[1];  // [8,19,128,128]
    float* out = (float*)d_out;                  // [8,512,19,1]

    cudaFuncSetAttribute(gather_kernel,
                         cudaFuncAttributeMaxDynamicSharedMemorySize, SMEM_BYTES);

    softmax_stats_kernel<<<B * K, 512>>>(aux);
    dim3 grid(C / CT, B, ZSPLIT);
    gather_kernel<<<grid, 256, SMEM_BYTES>>>(feats);
    reduce_kernel<<<(B * C * K + 255) / 256, 256>>>(out);
}